// round 2
// baseline (speedup 1.0000x reference)
#include <cuda_runtime.h>
#include <cuda_bf16.h>
#include <math.h>

// WaveletAttention: y = x * sigmoid(relu(mean(dwt2_ll(x)) @ W1^T) @ W2^T)
// x [8,256,256,256] f32 (512 MB), W1 [16,256], W2 [256,16].
//
// mean(dwt2_ll(x)) == (1/135^2) * sum_{i,j} w[i]*w[j]*x[b,c,i,j]  (separable,
// linear), w = fixed length-256 vector from db8 dec_lo + symmetric pad.
//
// R2 strategy: batch-serial pipeline. One batch of x (64 MB) fits in L2
// (126 MB). reduce_b pulls x[b] through L2; scale_b re-reads it (L2 hits)
// and writes out[b] with evict-first stores. DRAM traffic: 1.5 GB -> 1.0 GB.

#define PLANE   65536          // 256*256 floats per (b,c)
#define PLANE4  16384          // float4 per plane
#define NBC     2048
#define INV_MEAN (1.0f/(135.0f*135.0f))

__device__ float g_y[NBC];     // weighted spatial means

// pywt db8 dec_lo, 16 taps
__constant__ float c_f[16] = {
    -0.00011747678400228192f, 0.0006754494059985568f, -0.0003917403729959771f,
    -0.00487035299301066f, 0.008746094047015655f, 0.013981027917015516f,
    -0.04408825393106472f, -0.01736930100202211f, 0.128747426620186f,
    0.00047248457399797254f, -0.2840155429624281f, -0.015829105256023893f,
    0.5853546836548691f, 0.6756307362980128f, 0.3128715909144659f,
    0.05441584224308161f
};

__device__ __forceinline__ float wcontrib(int q) {
    float s = 0.f;
#pragma unroll
    for (int k = 0; k < 16; ++k) {
        int qk = q + k;
        bool ok = ((qk & 1) == 0) && (qk >= 16) && (qk <= 284);
        s += ok ? c_f[k] : 0.f;
    }
    return s;
}
__device__ __forceinline__ float weight_at(int i) {
    return wcontrib(i + 15) + wcontrib(14 - i) + wcontrib(526 - i);
}

// ---------------------------------------------------------------------------
// reduce_b: one block per plane of batch b (grid 256). Reads 64 MB -> L2.
// ---------------------------------------------------------------------------
__global__ void __launch_bounds__(256) reduce_kernel(const float* __restrict__ x,
                                                     int b) {
    __shared__ float sw[256];
    __shared__ float red[8];
    const int t = threadIdx.x;

    sw[t] = weight_at(t);
    __syncthreads();

    const int bc = b * 256 + blockIdx.x;
    const float4* __restrict__ p = (const float4*)x + (size_t)bc * PLANE4;

    const int jc = (t & 63) * 4;
    const float w0 = sw[jc + 0], w1 = sw[jc + 1], w2 = sw[jc + 2], w3 = sw[jc + 3];
    const int ibase = t >> 6;

    float acc = 0.f;
#pragma unroll 8
    for (int it = 0; it < 64; ++it) {
        float4 v = p[it * 256 + t];
        float wi = sw[ibase + it * 4];
        acc += wi * (w0 * v.x + w1 * v.y + w2 * v.z + w3 * v.w);
    }

#pragma unroll
    for (int o = 16; o; o >>= 1) acc += __shfl_down_sync(0xffffffffu, acc, o);
    if ((t & 31) == 0) red[t >> 5] = acc;
    __syncthreads();
    if (t < 8) {
        float v = red[t];
#pragma unroll
        for (int o = 4; o; o >>= 1) v += __shfl_down_sync(0xffu, v, o);
        if (t == 0) g_y[bc] = v * INV_MEAN;
    }
}

// ---------------------------------------------------------------------------
// scale_b: grid (4, 256) — 4 blocks per plane, channel = blockIdx.y.
// Inline FC (redundant per block, ~4K FMA). x read via ld.cs (L2 hit,
// evict-first after), out written via st.cs (don't pollute L2).
// ---------------------------------------------------------------------------
__global__ void __launch_bounds__(256) scale_kernel(const float* __restrict__ x,
                                                    float* __restrict__ out,
                                                    const float* __restrict__ W1,
                                                    const float* __restrict__ W2,
                                                    int b) {
    __shared__ float red[256];
    __shared__ float sh_h[16];
    __shared__ float s_b;

    const int t = threadIdx.x;
    const int c = blockIdx.y;
    const int bc = b * 256 + c;

    // ---- inline FC: h[u] = relu(sum_c y[b,c] * W1[u,c]); s = sigmoid(h . W2[c]) ----
    {
        const float* yb = g_y + b * 256;
        const int u = t >> 4, k = t & 15;        // 16 partials per u
        float part = 0.f;
        const float* w1 = W1 + u * 256 + k * 16;
        const float* yy = yb + k * 16;
#pragma unroll
        for (int j = 0; j < 16; ++j) part += yy[j] * w1[j];
        red[t] = part;
        __syncthreads();
        if (t < 16) {
            float s = 0.f;
#pragma unroll
            for (int j = 0; j < 16; ++j) s += red[t * 16 + j];
            sh_h[t] = fmaxf(s, 0.f);
        }
        __syncthreads();
        if (t == 0) {
            float s = 0.f;
            const float* w2 = W2 + c * 16;
#pragma unroll
            for (int u2 = 0; u2 < 16; ++u2) s += sh_h[u2] * w2[u2];
            s_b = 1.f / (1.f + expf(-s));
        }
        __syncthreads();
    }
    const float s = s_b;

    const float4* __restrict__ px = (const float4*)x + (size_t)bc * PLANE4
                                    + blockIdx.x * 4096;
    float4* __restrict__ po = (float4*)out + (size_t)bc * PLANE4
                              + blockIdx.x * 4096;
#pragma unroll
    for (int r = 0; r < 16; ++r) {
        float4 v = __ldcs(px + r * 256 + t);     // L2 hit from reduce_b, evict-first
        v.x *= s; v.y *= s; v.z *= s; v.w *= s;
        __stcs(po + r * 256 + t, v);             // streaming store
    }
}

extern "C" void kernel_launch(void* const* d_in, const int* in_sizes, int n_in,
                              void* d_out, int out_size) {
    const float* x  = (const float*)d_in[0];
    const float* W1 = (const float*)d_in[1];   // [16,256]
    const float* W2 = (const float*)d_in[2];   // [256,16]
    float* out = (float*)d_out;

    for (int b = 0; b < 8; ++b) {
        reduce_kernel<<<256, 256>>>(x, b);
        scale_kernel<<<dim3(4, 256), 256>>>(x, out, W1, W2, b);
    }
}

// round 3
// speedup vs baseline: 1.0683x; 1.0683x over previous
#include <cuda_runtime.h>
#include <cuda_bf16.h>
#include <math.h>

// WaveletAttention: out = x * sigmoid(relu(mean(dwt2_ll(x)) @ W1^T) @ W2^T)
// x [8,256,256,256] f32 (512 MB), W1 [16,256], W2 [256,16].
//
// mean(dwt2_ll(x)) == (1/135^2) * sum_{i,j} w[i]*w[j]*x[b,c,i,j]  (linear +
// separable), w = fixed 256-weight vector from db8 dec_lo, symmetric pad.
//
// R3: single persistent kernel, block-level producer/consumer pipeline over
// batches. 192 reducer blocks stream x[b] into L2 and accumulate the weighted
// means; 400 scaler blocks follow one batch behind, re-reading x[b] from L2
// (ld.cs) and writing out[b] (st.cs). DRAM traffic ~1.0 GB instead of 1.5 GB,
// with read and write streams fully overlapped. Window of 2 batches (128 MB)
// enforced by backpressure so x[b] survives in L2 (126 MB) until scaled.

#define PLANE4   16384         // float4 per 256x256 plane
#define NBC      2048
#define INV_MEAN (1.0f/(135.0f*135.0f))

#define GRID_G   592           // 4 blocks/SM * 148 SMs -> all co-resident
#define RBLK     192           // reducer blocks
#define SBLK     (GRID_G - RBLK)
#define NCHUNK   1024          // quarter-planes per batch (256 planes * 4)

__device__ float g_yraw[NBC];       // raw weighted sums (atomicAdd targets)
__device__ int   g_red_done[8];
__device__ int   g_scale_done[8];

// pywt db8 dec_lo, 16 taps
__constant__ float c_f[16] = {
    -0.00011747678400228192f, 0.0006754494059985568f, -0.0003917403729959771f,
    -0.00487035299301066f, 0.008746094047015655f, 0.013981027917015516f,
    -0.04408825393106472f, -0.01736930100202211f, 0.128747426620186f,
    0.00047248457399797254f, -0.2840155429624281f, -0.015829105256023893f,
    0.5853546836548691f, 0.6756307362980128f, 0.3128715909144659f,
    0.05441584224308161f
};

__device__ __forceinline__ float wcontrib(int q) {
    float s = 0.f;
#pragma unroll
    for (int k = 0; k < 16; ++k) {
        int qk = q + k;
        bool ok = ((qk & 1) == 0) && (qk >= 16) && (qk <= 284);
        s += ok ? c_f[k] : 0.f;
    }
    return s;
}
__device__ __forceinline__ float weight_at(int i) {
    return wcontrib(i + 15) + wcontrib(14 - i) + wcontrib(526 - i);
}

// Reset accumulators/flags (graph replays reuse device globals).
__global__ void init_kernel() {
    int i = blockIdx.x * blockDim.x + threadIdx.x;
    if (i < NBC) g_yraw[i] = 0.f;
    if (i < 8) { g_red_done[i] = 0; g_scale_done[i] = 0; }
}

__global__ void __launch_bounds__(256, 4)
fused_kernel(const float* __restrict__ x, float* __restrict__ out,
             const float* __restrict__ W1, const float* __restrict__ W2) {
    __shared__ float sw[256];
    __shared__ float red[256];
    __shared__ float sh_h[16];

    const int t = threadIdx.x;
    const int bid = blockIdx.x;

    if (bid < RBLK) {
        // ----------------------------- reducer -----------------------------
        sw[t] = weight_at(t);
        __syncthreads();
        const int jc = (t & 63) * 4;
        const float w0 = sw[jc], w1 = sw[jc + 1], w2 = sw[jc + 2], w3 = sw[jc + 3];
        const int rbase = t >> 6;

        for (int b = 0; b < 8; ++b) {
            if (b >= 2) {                       // backpressure: keep L2 window = 2
                if (t == 0) {
                    while (((volatile int*)g_scale_done)[b - 2] < SBLK) __nanosleep(128);
                }
                __syncthreads();
            }
            for (int ch = bid; ch < NCHUNK; ch += RBLK) {
                const int plane = ch >> 2, q = ch & 3;
                const float4* __restrict__ p =
                    (const float4*)x + ((size_t)(b * 256 + plane)) * PLANE4 + q * 4096;
                float acc = 0.f;
#pragma unroll
                for (int it = 0; it < 16; ++it) {
                    float4 v = p[it * 256 + t];
                    float wi = sw[q * 64 + rbase + it * 4];
                    acc += wi * (w0 * v.x + w1 * v.y + w2 * v.z + w3 * v.w);
                }
#pragma unroll
                for (int o = 16; o; o >>= 1) acc += __shfl_down_sync(0xffffffffu, acc, o);
                if ((t & 31) == 0) red[t >> 5] = acc;
                __syncthreads();
                if (t == 0) {
                    float v = 0.f;
#pragma unroll
                    for (int j = 0; j < 8; ++j) v += red[j];
                    atomicAdd(&g_yraw[b * 256 + plane], v);
                }
                __syncthreads();
            }
            __threadfence();
            if (t == 0) atomicAdd(&g_red_done[b], 1);
        }
    } else {
        // ----------------------------- scaler ------------------------------
        const int sid = bid - RBLK;
        for (int b = 0; b < 8; ++b) {
            if (t == 0) {
                while (((volatile int*)g_red_done)[b] < RBLK) __nanosleep(128);
            }
            __syncthreads();
            __threadfence();                    // acquire: g_yraw visible

            // FC layer 1: h[u] = relu(sum_c y[b,c] * W1[u,c])
            {
                const int u = t >> 4, k = t & 15;
                const float* w1p = W1 + u * 256 + k * 16;
                const float* yy = g_yraw + b * 256 + k * 16;
                float part = 0.f;
#pragma unroll
                for (int j = 0; j < 16; ++j) part += (yy[j] * INV_MEAN) * w1p[j];
                red[t] = part;
                __syncthreads();
                if (t < 16) {
                    float s = 0.f;
#pragma unroll
                    for (int j = 0; j < 16; ++j) s += red[t * 16 + j];
                    sh_h[t] = fmaxf(s, 0.f);
                }
                __syncthreads();
            }

            for (int ch = sid; ch < NCHUNK; ch += SBLK) {
                const int plane = ch >> 2, q = ch & 3;
                // s[b,plane] = sigmoid(h . W2[plane,:])  (redundant per thread, cheap)
                float sv = 0.f;
                const float* w2p = W2 + plane * 16;
#pragma unroll
                for (int u = 0; u < 16; ++u) sv += sh_h[u] * w2p[u];
                sv = 1.f / (1.f + expf(-sv));

                const size_t base = ((size_t)(b * 256 + plane)) * PLANE4 + q * 4096;
                const float4* __restrict__ px = (const float4*)x + base;
                float4* __restrict__ po = (float4*)out + base;
#pragma unroll
                for (int r = 0; r < 16; ++r) {
                    float4 v = __ldcs(px + r * 256 + t);   // L2 hit, evict-first
                    v.x *= sv; v.y *= sv; v.z *= sv; v.w *= sv;
                    __stcs(po + r * 256 + t, v);           // streaming store
                }
            }
            __threadfence();
            if (t == 0) atomicAdd(&g_scale_done[b], 1);
            __syncthreads();
        }
    }
}

extern "C" void kernel_launch(void* const* d_in, const int* in_sizes, int n_in,
                              void* d_out, int out_size) {
    const float* x  = (const float*)d_in[0];
    const float* W1 = (const float*)d_in[1];   // [16,256]
    const float* W2 = (const float*)d_in[2];   // [256,16]
    float* out = (float*)d_out;

    init_kernel<<<8, 256>>>();
    fused_kernel<<<GRID_G, 256>>>(x, out, W1, W2);
}

// round 4
// speedup vs baseline: 1.2058x; 1.1287x over previous
#include <cuda_runtime.h>
#include <cuda_bf16.h>
#include <math.h>

// WaveletAttention: out = x * sigmoid(relu(mean(dwt2_ll(x)) @ W1^T) @ W2^T)
// x [8,256,256,256] f32 (512 MB), W1 [16,256], W2 [256,16].
//
// mean(dwt2_ll(x)) == (1/135^2) * sum_{i,j} w[i]*w[j]*x[b,c,i,j]  (linear +
// separable), w = fixed 256-weight vector from db8 dec_lo, symmetric pad.
//
// R4: one persistent kernel, phase-locked per batch via a grid barrier.
//   reduce x[b] (64 MB -> L2, evict-normal)  |barrier|  FC + scale x[b]
//   (reads hit L2 via ld.cs, writes st.cs), then roll into reduce(b+1).
// Tight one-batch L2 window (64 MB << 126 MB) is what R3's loose pipeline
// lacked. Target DRAM traffic: 512 MB read + 512 MB write.

#define PLANE4   16384u        // float4 per 256x256 plane
#define NBC      2048
#define INV_MEAN (1.0f/(135.0f*135.0f))

#define GRID_G   592           // 4 blocks/SM * 148 SMs -> all co-resident
#define NCH      4096          // 1/16-plane chunks per batch (256 planes * 16)

__device__ float g_yraw[NBC];          // raw weighted sums (atomicAdd targets)
__device__ int   g_bar_count;
__device__ int   g_bar_phase;

// pywt db8 dec_lo, 16 taps
__constant__ float c_f[16] = {
    -0.00011747678400228192f, 0.0006754494059985568f, -0.0003917403729959771f,
    -0.00487035299301066f, 0.008746094047015655f, 0.013981027917015516f,
    -0.04408825393106472f, -0.01736930100202211f, 0.128747426620186f,
    0.00047248457399797254f, -0.2840155429624281f, -0.015829105256023893f,
    0.5853546836548691f, 0.6756307362980128f, 0.3128715909144659f,
    0.05441584224308161f
};

__device__ __forceinline__ float wcontrib(int q) {
    float s = 0.f;
#pragma unroll
    for (int k = 0; k < 16; ++k) {
        int qk = q + k;
        bool ok = ((qk & 1) == 0) && (qk >= 16) && (qk <= 284);
        s += ok ? c_f[k] : 0.f;
    }
    return s;
}
__device__ __forceinline__ float weight_at(int i) {
    return wcontrib(i + 15) + wcontrib(14 - i) + wcontrib(526 - i);
}

// Reset device state for each graph replay.
__global__ void init_kernel() {
    int i = blockIdx.x * blockDim.x + threadIdx.x;
    if (i < NBC) g_yraw[i] = 0.f;
    if (i == 0) { g_bar_count = 0; g_bar_phase = 0; }
}

__global__ void __launch_bounds__(256, 4)
fused_kernel(const float* __restrict__ x, float* __restrict__ out,
             const float* __restrict__ W1, const float* __restrict__ W2) {
    __shared__ float sw[256];
    __shared__ float red[256];
    __shared__ float sh_h[16];

    const int t = threadIdx.x;
    const int bid = blockIdx.x;

    sw[t] = weight_at(t);
    __syncthreads();

    const int jc = (t & 63) * 4;
    const float w0 = sw[jc], w1 = sw[jc + 1], w2 = sw[jc + 2], w3 = sw[jc + 3];
    const int rb = t >> 6;                 // row sub-offset within a 4-row group

    for (int b = 0; b < 8; ++b) {
        // ----------------- phase 1: weighted reduction of x[b] -----------------
        for (int ch = bid; ch < NCH; ch += GRID_G) {
            const int plane = ch >> 4, q = ch & 15;   // 16 rows per chunk
            const float4* __restrict__ p =
                (const float4*)x + ((size_t)(b * 256 + plane)) * PLANE4 + q * 1024;
            float acc = 0.f;
#pragma unroll
            for (int it = 0; it < 4; ++it) {
                float4 v = p[it * 256 + t];           // evict-normal: stays in L2
                float wi = sw[q * 16 + it * 4 + rb];
                acc += wi * (w0 * v.x + w1 * v.y + w2 * v.z + w3 * v.w);
            }
#pragma unroll
            for (int o = 16; o; o >>= 1) acc += __shfl_down_sync(0xffffffffu, acc, o);
            if ((t & 31) == 0) red[t >> 5] = acc;
            __syncthreads();
            if (t == 0) {
                float v = red[0] + red[1] + red[2] + red[3]
                        + red[4] + red[5] + red[6] + red[7];
                atomicAdd(&g_yraw[b * 256 + plane], v);
            }
            __syncthreads();
        }

        // ------------------------- grid barrier (b) ----------------------------
        if (t == 0) {
            __threadfence();
            if (atomicAdd(&g_bar_count, 1) == GRID_G - 1) {
                atomicExch(&g_bar_count, 0);
                __threadfence();
                atomicExch(&g_bar_phase, b + 1);
            } else {
                while (atomicAdd(&g_bar_phase, 0) <= b) __nanosleep(64);
            }
        }
        __syncthreads();

        // ---------------- phase 2: FC (per block) + scale x[b] -----------------
        {
            const int u = t >> 4, k = t & 15;
            const float* w1p = W1 + u * 256 + k * 16;
            const float* yy = g_yraw + b * 256 + k * 16;
            float part = 0.f;
#pragma unroll
            for (int j = 0; j < 16; ++j) part += (yy[j] * INV_MEAN) * w1p[j];
            red[t] = part;
            __syncthreads();
            if (t < 16) {
                float s = 0.f;
#pragma unroll
                for (int j = 0; j < 16; ++j) s += red[t * 16 + j];
                sh_h[t] = fmaxf(s, 0.f);
            }
            __syncthreads();
        }

        for (int ch = bid; ch < NCH; ch += GRID_G) {
            const int plane = ch >> 4, q = ch & 15;
            float sv = 0.f;
            const float* w2p = W2 + plane * 16;
#pragma unroll
            for (int u = 0; u < 16; ++u) sv += sh_h[u] * w2p[u];
            sv = 1.f / (1.f + expf(-sv));

            const size_t base = ((size_t)(b * 256 + plane)) * PLANE4 + q * 1024;
            const float4* __restrict__ px = (const float4*)x + base;
            float4* __restrict__ po = (float4*)out + base;
#pragma unroll
            for (int it = 0; it < 4; ++it) {
                float4 v = __ldcs(px + it * 256 + t);   // L2 hit, then evict-first
                v.x *= sv; v.y *= sv; v.z *= sv; v.w *= sv;
                __stcs(po + it * 256 + t, v);           // streaming store
            }
        }
        __syncthreads();
        // no barrier here: roll into reduce(b+1); write/read streams overlap
    }
}

extern "C" void kernel_launch(void* const* d_in, const int* in_sizes, int n_in,
                              void* d_out, int out_size) {
    const float* x  = (const float*)d_in[0];
    const float* W1 = (const float*)d_in[1];   // [16,256]
    const float* W2 = (const float*)d_in[2];   // [256,16]
    float* out = (float*)d_out;

    init_kernel<<<8, 256>>>();
    fused_kernel<<<GRID_G, 256>>>(x, out, W1, W2);
}